// round 15
// baseline (speedup 1.0000x reference)
#include <cuda_runtime.h>
#include <cuda_bf16.h>
#include <cstdint>

#define NN 64
#define CI 256
#define CO 256
#define CR 32
#define TT 64
#define VV 25
#define TV 1600   // T*V
#define UV 625    // V*V

// ---------------- scratch ----------------
__device__ float g_xm[NN*CI*VV];
__device__ float g_x1[NN*CR*VV];
__device__ float g_x2[NN*CR*VV];
__device__ float g_aff[NN*CR*UV];
__device__ float g_attn[NN*CO*UV];     // (n, co, u*25+v)
__device__ __nv_bfloat16 g_bhi[CO*CI]; // bf16(w3)    [co, c]
__device__ __nv_bfloat16 g_blo[CO*CI];

// ---------------- helpers ----------------
__device__ __forceinline__ uint32_t smem_u32(const void* p) {
    uint32_t a;
    asm("{ .reg .u64 t; cvta.to.shared.u64 t, %1; cvt.u32.u64 %0, t; }" : "=r"(a) : "l"(p));
    return a;
}
#define CPA(dst, src) asm volatile("cp.async.cg.shared.global [%0], [%1], 16;" \
                                   :: "r"(dst), "l"(src) : "memory")
#define CPC() asm volatile("cp.async.commit_group;" ::: "memory")
#define CPW(n) asm volatile("cp.async.wait_group %0;" :: "n"(n) : "memory")

__device__ __forceinline__ void ldsm4(uint32_t& r0, uint32_t& r1, uint32_t& r2, uint32_t& r3,
                                      uint32_t a) {
    asm volatile("ldmatrix.sync.aligned.m8n8.x4.shared.b16 {%0,%1,%2,%3}, [%4];"
                 : "=r"(r0), "=r"(r1), "=r"(r2), "=r"(r3) : "r"(a));
}
__device__ __forceinline__ void mma16816(float* d, const uint32_t* a, const uint32_t* b) {
    asm volatile("mma.sync.aligned.m16n8k16.row.col.f32.bf16.bf16.f32 "
                 "{%0,%1,%2,%3}, {%4,%5,%6,%7}, {%8,%9}, {%0,%1,%2,%3};"
                 : "+f"(d[0]), "+f"(d[1]), "+f"(d[2]), "+f"(d[3])
                 : "r"(a[0]), "r"(a[1]), "r"(a[2]), "r"(a[3]), "r"(b[0]), "r"(b[1]));
}

// ---------------- K: xm = mean_t x ----------------
__global__ void k_xm(const float* __restrict__ x) {
    __shared__ float sx[4*TV];
    int n = blockIdx.y, cc = blockIdx.x;
    const float* xb = x + ((size_t)(n*CI + cc*4))*TV;
    for (int i = threadIdx.x; i < 4*TV; i += 256) sx[i] = xb[i];
    __syncthreads();
    if (threadIdx.x < 100) {
        int c = threadIdx.x / VV, v = threadIdx.x - c*VV;
        float s = 0.f;
        #pragma unroll
        for (int t = 0; t < TT; t++) s += sx[c*TV + t*VV + v];
        g_xm[n*(CI*VV) + cc*100 + threadIdx.x] = s * (1.0f/64.0f);
    }
}

// ---------------- K: x1/x2 ----------------
__global__ void k_x12(const float* __restrict__ w1, const float* __restrict__ b1,
                      const float* __restrict__ w2, const float* __restrict__ b2) {
    __shared__ float xm_s[CI*VV];
    int n = blockIdx.x;
    for (int i = threadIdx.x; i < CI*VV; i += 256) xm_s[i] = g_xm[n*(CI*VV) + i];
    __syncthreads();
    for (int i = threadIdx.x; i < 2*CR*VV; i += 256) {
        int sel = i / (CR*VV);
        int rv  = i - sel*(CR*VV);
        int r = rv / VV, v = rv - r*VV;
        const float* w = sel ? w2 : w1;
        float s = sel ? b2[r] : b1[r];
        #pragma unroll 8
        for (int c = 0; c < CI; c++) s += w[r*CI + c] * xm_s[c*VV + v];
        (sel ? g_x2 : g_x1)[n*(CR*VV) + rv] = s;
    }
}

// ---------------- K: aff = tanh(x1[u] - x2[v]) ----------------
__global__ void k_aff() {
    __shared__ float s1[CR*VV], s2[CR*VV];
    int n = blockIdx.x;
    for (int i = threadIdx.x; i < CR*VV; i += 256) {
        s1[i] = g_x1[n*(CR*VV) + i];
        s2[i] = g_x2[n*(CR*VV) + i];
    }
    __syncthreads();
    for (int i = threadIdx.x; i < CR*UV; i += 256) {
        int r = i / UV, uv = i - r*UV;
        int u = uv / VV, v = uv - u*VV;
        g_aff[n*(CR*UV) + i] = tanhf(s1[r*VV + u] - s2[r*VV + v]);
    }
}

// ---------------- K: attn = w4@aff + b4 + A  (w4 transposed in smem) ----------------
__global__ void k_attn(const float* __restrict__ w4, const float* __restrict__ b4,
                       const float* __restrict__ A) {
    __shared__ __align__(16) float w4s[CR*66];
    __shared__ __align__(16) float affs[CR*64];
    int n = blockIdx.z, cot = blockIdx.y, uvt = blockIdx.x;
    int co0 = cot*64, uv0 = uvt*64;
    int tx = threadIdx.x & 15, ty = threadIdx.x >> 4;

    for (int i = threadIdx.x; i < 64*CR; i += 256) {
        int co = i >> 5, k = i & 31;
        w4s[k*66 + co] = w4[(co0 + co)*CR + k];
    }
    for (int i = threadIdx.x; i < CR*64; i += 256) {
        int r = i >> 6, c = i & 63;
        affs[i] = (uv0 + c < UV) ? g_aff[n*(CR*UV) + r*UV + uv0 + c] : 0.f;
    }
    __syncthreads();

    float acc[4][4] = {};
    #pragma unroll
    for (int k = 0; k < CR; k++) {
        float4 b = *(const float4*)&affs[k*64 + tx*4];
        float2 a01 = *(const float2*)&w4s[k*66 + ty*4];
        float2 a23 = *(const float2*)&w4s[k*66 + ty*4 + 2];
        float av[4] = {a01.x, a01.y, a23.x, a23.y};
        #pragma unroll
        for (int i = 0; i < 4; i++) {
            acc[i][0] += av[i]*b.x; acc[i][1] += av[i]*b.y;
            acc[i][2] += av[i]*b.z; acc[i][3] += av[i]*b.w;
        }
    }
    #pragma unroll
    for (int i = 0; i < 4; i++) {
        int co = co0 + ty*4 + i;
        float bb = b4[co];
        #pragma unroll
        for (int j = 0; j < 4; j++) {
            int uv = uv0 + tx*4 + j;
            if (uv < UV)
                g_attn[((size_t)n*CO + co)*UV + uv] = acc[i][j] + bb + A[uv];
        }
    }
}

// ---------------- K: w3 split ----------------
__global__ void k_w3cvt(const float* __restrict__ w3) {
    int i = blockIdx.x*1024 + threadIdx.x;
    float v = w3[i];
    __nv_bfloat16 hi = __float2bfloat16(v);
    g_bhi[i] = hi;
    g_blo[i] = __float2bfloat16(v - __bfloat162float(hi));
}

// ---------------- K: fused convert + HMMA GEMM + graph contraction ----------------
// grid (13 tiles, 64 n); CTA: 125 tv rows (= 5 t) x 256 co, K=256 in 8 chunks of 32.
// A loads from 16B-aligned base tvA = tv0 - pad; only truly-OOB slots clamped.
#define XF_OFF 0
#define XF_SZ  16384
#define A_OFF  32768
#define A_SZ   20480
#define AL_OFF 10240
#define B_OFF  73728
#define B_SZ   40960
#define BL_OFF 20480
#define MMA_SMEM 196608
#define X3_STRIDE 264

__global__ __launch_bounds__(512, 1) void k_mma(const float* __restrict__ x,
                                                const float* __restrict__ b3,
                                                float* __restrict__ out) {
    extern __shared__ __align__(1024) char smem[];
    uint32_t sb = smem_u32(smem);
    int tid = threadIdx.x, lane = tid & 31, wid = tid >> 5;
    int tile = blockIdx.x, n = blockIdx.y;
    int tv0 = tile * 125;
    int rows = (TV - tv0 >= 125) ? 125 : (TV - tv0);   // 125, last tile: 100
    int pad = tv0 & 3;                                 // = tile & 3
    int tvA = tv0 - pad;                               // 16B-aligned base
    const float* xb = x + ((size_t)n*CI)*TV + tvA;

    auto loadX = [&](int kb, int s) {
        uint32_t xo = sb + XF_OFF + s*XF_SZ;
        #pragma unroll
        for (int it = 0; it < 2; it++) {
            int idx = tid + it*512;
            int c = idx >> 5, q = idx & 31;
            // clamp ONLY slots that would read past this (n,c) row's end (last tile only)
            int tq = (tvA + q*4 + 4 <= TV) ? q : 0;
            CPA(xo + c*512 + q*16, xb + (size_t)(kb*32 + c)*TV + tq*4);
        }
    };
    auto loadB = [&](int kb, int bs) {
        uint32_t bo = sb + B_OFF + bs*B_SZ;
        #pragma unroll
        for (int it = 0; it < 4; it++) {
            int idx = tid + it*512;
            int split = idx >> 10, r = idx & 1023;
            int co = r >> 2, q = r & 3;
            const __nv_bfloat16* src = (split ? g_blo : g_bhi) + co*256 + kb*32 + q*8;
            CPA(bo + split*BL_OFF + co*80 + q*16, src);
        }
    };
    auto convert = [&](int s) {
        const char* xf = smem + XF_OFF + s*XF_SZ;
        char* ad = smem + A_OFF + s*A_SZ;
        int tv = tid & 127, cg = tid >> 7;
        int tvi = (tv + pad <= 127) ? tv + pad : 127;   // stay inside XF column
        const float* col = (const float*)(xf + cg*8*512 + tvi*4);
        uint32_t hi[4], lo[4];
        #pragma unroll
        for (int j = 0; j < 4; j++) {
            float v0 = col[(2*j)*128];
            float v1 = col[(2*j+1)*128];
            __nv_bfloat16 h0 = __float2bfloat16(v0), h1 = __float2bfloat16(v1);
            __nv_bfloat162 hh; hh.x = h0; hh.y = h1;
            __nv_bfloat162 ll;
            ll.x = __float2bfloat16(v0 - __bfloat162float(h0));
            ll.y = __float2bfloat16(v1 - __bfloat162float(h1));
            hi[j] = *(uint32_t*)&hh;
            lo[j] = *(uint32_t*)&ll;
        }
        *(uint4*)(ad + tv*80 + cg*16)          = make_uint4(hi[0],hi[1],hi[2],hi[3]);
        *(uint4*)(ad + AL_OFF + tv*80 + cg*16) = make_uint4(lo[0],lo[1],lo[2],lo[3]);
    };

    loadX(0, 0); loadB(0, 0); CPC();
    loadX(1, 1); loadB(1, 1); CPC();

    int m0 = (wid & 3)*32, n0 = (wid >> 2)*64;
    float acc[2][8][4];
    #pragma unroll
    for (int mt = 0; mt < 2; mt++)
        #pragma unroll
        for (int nt = 0; nt < 8; nt++)
            #pragma unroll
            for (int k = 0; k < 4; k++) acc[mt][nt][k] = 0.f;

    int a_row = lane & 15, a_seg = lane >> 4;
    int b_row = ((lane >> 4) & 1)*8 + (lane & 7), b_seg = (lane >> 3) & 1;

    #pragma unroll
    for (int kb = 0; kb < 8; kb++) {
        if (kb < 7) { CPW(1); } else { CPW(0); }
        __syncthreads();
        convert(kb & 1);
        __syncthreads();
        if (kb < 6) { loadX(kb + 2, kb & 1); loadB(kb + 2, (kb + 2) % 3); CPC(); }
        uint32_t ao = sb + A_OFF + (kb & 1)*A_SZ;
        uint32_t bo = sb + B_OFF + (kb % 3)*B_SZ;
        #pragma unroll
        for (int ks = 0; ks < 2; ks++) {
            uint32_t ah[2][4], al[2][4], bh[16], bl[16];
            #pragma unroll
            for (int mt = 0; mt < 2; mt++) {
                uint32_t off = (uint32_t)((m0 + mt*16 + a_row)*80 + ks*32 + a_seg*16);
                ldsm4(ah[mt][0], ah[mt][1], ah[mt][2], ah[mt][3], ao + off);
                ldsm4(al[mt][0], al[mt][1], al[mt][2], al[mt][3], ao + AL_OFF + off);
            }
            #pragma unroll
            for (int np = 0; np < 4; np++) {
                uint32_t off = (uint32_t)((n0 + np*16 + b_row)*80 + ks*32 + b_seg*16);
                ldsm4(bh[np*4+0], bh[np*4+1], bh[np*4+2], bh[np*4+3], bo + off);
                ldsm4(bl[np*4+0], bl[np*4+1], bl[np*4+2], bl[np*4+3], bo + BL_OFF + off);
            }
            #pragma unroll
            for (int mt = 0; mt < 2; mt++)
                #pragma unroll
                for (int nt = 0; nt < 8; nt++) {
                    mma16816(acc[mt][nt], ah[mt], &bh[nt*2]);
                    mma16816(acc[mt][nt], ah[mt], &bl[nt*2]);
                    mma16816(acc[mt][nt], al[mt], &bh[nt*2]);
                }
        }
    }

    // ---- x3 (+b3) to smem fp32, reusing pipeline buffers ----
    __syncthreads();
    float* x3s = (float*)smem;   // [128][X3_STRIDE]
    #pragma unroll
    for (int mt = 0; mt < 2; mt++) {
        int r0 = m0 + mt*16 + (lane >> 2);
        #pragma unroll
        for (int nt = 0; nt < 8; nt++) {
            int c = n0 + nt*8 + (lane & 3)*2;
            float2 bb = *(const float2*)(b3 + c);
            x3s[(r0    )*X3_STRIDE + c    ] = acc[mt][nt][0] + bb.x;
            x3s[(r0    )*X3_STRIDE + c + 1] = acc[mt][nt][1] + bb.y;
            x3s[(r0 + 8)*X3_STRIDE + c    ] = acc[mt][nt][2] + bb.x;
            x3s[(r0 + 8)*X3_STRIDE + c + 1] = acc[mt][nt][3] + bb.y;
        }
    }
    __syncthreads();

    // ---- contraction: out[n,co,t,v] = sum_u attn[n,co,u,v] * x3s[t*25+u][co] ----
    int t_cnt = rows / VV;          // 5 (or 4 on last tile)
    int t0g = tile * 5;
    #pragma unroll 1
    for (int ci = 0; ci < 16; ci++) {
        int co = wid*16 + ci;
        const float* ap = g_attn + ((size_t)n*CO + co)*UV;
        float a[VV];
        #pragma unroll
        for (int u = 0; u < VV; u++)
            a[u] = (lane < VV) ? ap[u*VV + lane] : 0.f;
        float* ob = out + (((size_t)(n*CO + co))*TT + t0g)*VV + lane;
        for (int t = 0; t < t_cnt; t++) {
            const float* xr = x3s + (t*VV)*X3_STRIDE + co;
            float s = 0.f;
            #pragma unroll
            for (int u = 0; u < VV; u++)
                s += a[u] * xr[u*X3_STRIDE];
            if (lane < VV) ob[(size_t)t*VV] = s;
        }
    }
}

// ---------------- launch ----------------
extern "C" void kernel_launch(void* const* d_in, const int* in_sizes, int n_in,
                              void* d_out, int out_size) {
    const float* x  = (const float*)d_in[0];
    const float* A  = (const float*)d_in[1];
    const float* w1 = (const float*)d_in[2];
    const float* b1 = (const float*)d_in[3];
    const float* w2 = (const float*)d_in[4];
    const float* b2 = (const float*)d_in[5];
    const float* w3 = (const float*)d_in[6];
    const float* b3 = (const float*)d_in[7];
    const float* w4 = (const float*)d_in[8];
    const float* b4 = (const float*)d_in[9];
    float* out = (float*)d_out;

    cudaFuncSetAttribute(k_mma, cudaFuncAttributeMaxDynamicSharedMemorySize, MMA_SMEM);

    k_xm   <<<dim3(64, 64), 256>>>(x);            // 1
    k_x12  <<<64, 256>>>(w1, b1, w2, b2);         // 2
    k_aff  <<<64, 256>>>();                       // 3
    k_attn <<<dim3(10, 4, 64), 256>>>(w4, b4, A); // 4  <-- profiled
    k_w3cvt<<<64, 1024>>>(w3);                    // 5
    k_mma  <<<dim3(13, 64), 512, MMA_SMEM>>>(x, b3, out); // 6
}

// round 16
// speedup vs baseline: 1.0742x; 1.0742x over previous
#include <cuda_runtime.h>
#include <cuda_bf16.h>
#include <cuda_fp16.h>
#include <cstdint>

#define NN 64
#define CI 256
#define CO 256
#define CR 32
#define TT 64
#define VV 25
#define TV 1600   // T*V
#define UV 625    // V*V
#define NROWS (NN*TV)       // 102400

// ---------------- scratch ----------------
__device__ float g_xm[NN*CI*VV];
__device__ float g_x1[NN*CR*VV];
__device__ float g_x2[NN*CR*VV];
__device__ float g_aff[NN*CR*UV];
__device__ float g_attn[NN*CO*UV];     // (n, co, u*25+v)
__device__ __nv_bfloat16 g_bhi[CO*CI]; // bf16(w3)    [co, c]
__device__ __nv_bfloat16 g_blo[CO*CI];
__device__ __half g_x3h[(size_t)NROWS*CO]; // fp16, layout: [n][co/8][tv][co%8]

// ---------------- helpers ----------------
__device__ __forceinline__ uint32_t smem_u32(const void* p) {
    uint32_t a;
    asm("{ .reg .u64 t; cvta.to.shared.u64 t, %1; cvt.u32.u64 %0, t; }" : "=r"(a) : "l"(p));
    return a;
}
#define CPA(dst, src) asm volatile("cp.async.cg.shared.global [%0], [%1], 16;" \
                                   :: "r"(dst), "l"(src) : "memory")
#define CPC() asm volatile("cp.async.commit_group;" ::: "memory")
#define CPW(n) asm volatile("cp.async.wait_group %0;" :: "n"(n) : "memory")

__device__ __forceinline__ void ldsm4(uint32_t& r0, uint32_t& r1, uint32_t& r2, uint32_t& r3,
                                      uint32_t a) {
    asm volatile("ldmatrix.sync.aligned.m8n8.x4.shared.b16 {%0,%1,%2,%3}, [%4];"
                 : "=r"(r0), "=r"(r1), "=r"(r2), "=r"(r3) : "r"(a));
}
__device__ __forceinline__ void mma16816(float* d, const uint32_t* a, const uint32_t* b) {
    asm volatile("mma.sync.aligned.m16n8k16.row.col.f32.bf16.bf16.f32 "
                 "{%0,%1,%2,%3}, {%4,%5,%6,%7}, {%8,%9}, {%0,%1,%2,%3};"
                 : "+f"(d[0]), "+f"(d[1]), "+f"(d[2]), "+f"(d[3])
                 : "r"(a[0]), "r"(a[1]), "r"(a[2]), "r"(a[3]), "r"(b[0]), "r"(b[1]));
}

// ---------------- K: xm = mean_t x ----------------
__global__ void k_xm(const float* __restrict__ x) {
    __shared__ float sx[4*TV];
    int n = blockIdx.y, cc = blockIdx.x;
    const float* xb = x + ((size_t)(n*CI + cc*4))*TV;
    for (int i = threadIdx.x; i < 4*TV; i += 256) sx[i] = xb[i];
    __syncthreads();
    if (threadIdx.x < 100) {
        int c = threadIdx.x / VV, v = threadIdx.x - c*VV;
        float s = 0.f;
        #pragma unroll
        for (int t = 0; t < TT; t++) s += sx[c*TV + t*VV + v];
        g_xm[n*(CI*VV) + cc*100 + threadIdx.x] = s * (1.0f/64.0f);
    }
}

// ---------------- K: x1/x2 ----------------
__global__ void k_x12(const float* __restrict__ w1, const float* __restrict__ b1,
                      const float* __restrict__ w2, const float* __restrict__ b2) {
    __shared__ float xm_s[CI*VV];
    int n = blockIdx.x;
    for (int i = threadIdx.x; i < CI*VV; i += 256) xm_s[i] = g_xm[n*(CI*VV) + i];
    __syncthreads();
    for (int i = threadIdx.x; i < 2*CR*VV; i += 256) {
        int sel = i / (CR*VV);
        int rv  = i - sel*(CR*VV);
        int r = rv / VV, v = rv - r*VV;
        const float* w = sel ? w2 : w1;
        float s = sel ? b2[r] : b1[r];
        #pragma unroll 8
        for (int c = 0; c < CI; c++) s += w[r*CI + c] * xm_s[c*VV + v];
        (sel ? g_x2 : g_x1)[n*(CR*VV) + rv] = s;
    }
}

// ---------------- K: aff = tanh(x1[u] - x2[v]) ----------------
__global__ void k_aff() {
    __shared__ float s1[CR*VV], s2[CR*VV];
    int n = blockIdx.x;
    for (int i = threadIdx.x; i < CR*VV; i += 256) {
        s1[i] = g_x1[n*(CR*VV) + i];
        s2[i] = g_x2[n*(CR*VV) + i];
    }
    __syncthreads();
    for (int i = threadIdx.x; i < CR*UV; i += 256) {
        int r = i / UV, uv = i - r*UV;
        int u = uv / VV, v = uv - u*VV;
        g_aff[n*(CR*UV) + i] = tanhf(s1[r*VV + u] - s2[r*VV + v]);
    }
}

// ---------------- K: attn = w4@aff + b4 + A  (w4 transposed in smem) ----------------
__global__ void k_attn(const float* __restrict__ w4, const float* __restrict__ b4,
                       const float* __restrict__ A) {
    __shared__ __align__(16) float w4s[CR*66];
    __shared__ __align__(16) float affs[CR*64];
    int n = blockIdx.z, cot = blockIdx.y, uvt = blockIdx.x;
    int co0 = cot*64, uv0 = uvt*64;
    int tx = threadIdx.x & 15, ty = threadIdx.x >> 4;

    for (int i = threadIdx.x; i < 64*CR; i += 256) {
        int co = i >> 5, k = i & 31;
        w4s[k*66 + co] = w4[(co0 + co)*CR + k];
    }
    for (int i = threadIdx.x; i < CR*64; i += 256) {
        int r = i >> 6, c = i & 63;
        affs[i] = (uv0 + c < UV) ? g_aff[n*(CR*UV) + r*UV + uv0 + c] : 0.f;
    }
    __syncthreads();

    float acc[4][4] = {};
    #pragma unroll
    for (int k = 0; k < CR; k++) {
        float4 b = *(const float4*)&affs[k*64 + tx*4];
        float2 a01 = *(const float2*)&w4s[k*66 + ty*4];
        float2 a23 = *(const float2*)&w4s[k*66 + ty*4 + 2];
        float av[4] = {a01.x, a01.y, a23.x, a23.y};
        #pragma unroll
        for (int i = 0; i < 4; i++) {
            acc[i][0] += av[i]*b.x; acc[i][1] += av[i]*b.y;
            acc[i][2] += av[i]*b.z; acc[i][3] += av[i]*b.w;
        }
    }
    #pragma unroll
    for (int i = 0; i < 4; i++) {
        int co = co0 + ty*4 + i;
        float bb = b4[co];
        #pragma unroll
        for (int j = 0; j < 4; j++) {
            int uv = uv0 + tx*4 + j;
            if (uv < UV)
                g_attn[((size_t)n*CO + co)*UV + uv] = acc[i][j] + bb + A[uv];
        }
    }
}

// ---------------- K: w3 split ----------------
__global__ void k_w3cvt(const float* __restrict__ w3) {
    int i = blockIdx.x*1024 + threadIdx.x;
    float v = w3[i];
    __nv_bfloat16 hi = __float2bfloat16(v);
    g_bhi[i] = hi;
    g_blo[i] = __float2bfloat16(v - __bfloat162float(hi));
}

// ---------------- K: fused convert + HMMA GEMM  x3 = x @ w3^T + b3 ----------------
#define XF_OFF 0
#define XF_SZ  16384
#define A_OFF  32768
#define A_SZ   20480
#define AL_OFF 10240
#define B_OFF  73728
#define B_SZ   40960
#define BL_OFF 20480
#define MMA_SMEM 196608

__global__ __launch_bounds__(512, 1) void k_mma(const float* __restrict__ x,
                                                const float* __restrict__ b3) {
    extern __shared__ __align__(1024) char smem[];
    uint32_t sb = smem_u32(smem);
    int tid = threadIdx.x, lane = tid & 31, wid = tid >> 5;
    int tile = blockIdx.x, n = blockIdx.y;
    int tv0 = tile * 128;
    int rows = (TV - tv0 >= 128) ? 128 : (TV - tv0);
    const float* xb = x + ((size_t)n*CI)*TV + tv0;

    auto loadX = [&](int kb, int s) {
        uint32_t xo = sb + XF_OFF + s*XF_SZ;
        #pragma unroll
        for (int it = 0; it < 2; it++) {
            int idx = tid + it*512;
            int c = idx >> 5, q = idx & 31;
            int tq = (q*4 < rows) ? q : 0;
            CPA(xo + c*512 + q*16, xb + (size_t)(kb*32 + c)*TV + tq*4);
        }
    };
    auto loadB = [&](int kb, int bs) {
        uint32_t bo = sb + B_OFF + bs*B_SZ;
        #pragma unroll
        for (int it = 0; it < 4; it++) {
            int idx = tid + it*512;
            int split = idx >> 10, r = idx & 1023;
            int co = r >> 2, q = r & 3;
            const __nv_bfloat16* src = (split ? g_blo : g_bhi) + co*256 + kb*32 + q*8;
            CPA(bo + split*BL_OFF + co*80 + q*16, src);
        }
    };
    auto convert = [&](int s) {
        const char* xf = smem + XF_OFF + s*XF_SZ;
        char* ad = smem + A_OFF + s*A_SZ;
        int tv = tid & 127, cg = tid >> 7;
        const float* col = (const float*)(xf + cg*8*512 + tv*4);
        uint32_t hi[4], lo[4];
        #pragma unroll
        for (int j = 0; j < 4; j++) {
            float v0 = col[(2*j)*128];
            float v1 = col[(2*j+1)*128];
            __nv_bfloat16 h0 = __float2bfloat16(v0), h1 = __float2bfloat16(v1);
            __nv_bfloat162 hh; hh.x = h0; hh.y = h1;
            __nv_bfloat162 ll;
            ll.x = __float2bfloat16(v0 - __bfloat162float(h0));
            ll.y = __float2bfloat16(v1 - __bfloat162float(h1));
            hi[j] = *(uint32_t*)&hh;
            lo[j] = *(uint32_t*)&ll;
        }
        *(uint4*)(ad + tv*80 + cg*16)          = make_uint4(hi[0],hi[1],hi[2],hi[3]);
        *(uint4*)(ad + AL_OFF + tv*80 + cg*16) = make_uint4(lo[0],lo[1],lo[2],lo[3]);
    };

    loadX(0, 0); loadB(0, 0); CPC();
    loadX(1, 1); loadB(1, 1); CPC();

    int m0 = (wid & 3)*32, n0 = (wid >> 2)*64;
    float acc[2][8][4];
    #pragma unroll
    for (int mt = 0; mt < 2; mt++)
        #pragma unroll
        for (int nt = 0; nt < 8; nt++)
            #pragma unroll
            for (int k = 0; k < 4; k++) acc[mt][nt][k] = 0.f;

    int a_row = lane & 15, a_seg = lane >> 4;
    int b_row = ((lane >> 4) & 1)*8 + (lane & 7), b_seg = (lane >> 3) & 1;

    #pragma unroll
    for (int kb = 0; kb < 8; kb++) {
        if (kb < 7) { CPW(1); } else { CPW(0); }
        __syncthreads();
        convert(kb & 1);
        __syncthreads();
        if (kb < 6) { loadX(kb + 2, kb & 1); loadB(kb + 2, (kb + 2) % 3); CPC(); }
        uint32_t ao = sb + A_OFF + (kb & 1)*A_SZ;
        uint32_t bo = sb + B_OFF + (kb % 3)*B_SZ;
        #pragma unroll
        for (int ks = 0; ks < 2; ks++) {
            uint32_t ah[2][4], al[2][4], bh[16], bl[16];
            #pragma unroll
            for (int mt = 0; mt < 2; mt++) {
                uint32_t off = (uint32_t)((m0 + mt*16 + a_row)*80 + ks*32 + a_seg*16);
                ldsm4(ah[mt][0], ah[mt][1], ah[mt][2], ah[mt][3], ao + off);
                ldsm4(al[mt][0], al[mt][1], al[mt][2], al[mt][3], ao + AL_OFF + off);
            }
            #pragma unroll
            for (int np = 0; np < 4; np++) {
                uint32_t off = (uint32_t)((n0 + np*16 + b_row)*80 + ks*32 + b_seg*16);
                ldsm4(bh[np*4+0], bh[np*4+1], bh[np*4+2], bh[np*4+3], bo + off);
                ldsm4(bl[np*4+0], bl[np*4+1], bl[np*4+2], bl[np*4+3], bo + BL_OFF + off);
            }
            #pragma unroll
            for (int mt = 0; mt < 2; mt++)
                #pragma unroll
                for (int nt = 0; nt < 8; nt++) {
                    mma16816(acc[mt][nt], ah[mt], &bh[nt*2]);
                    mma16816(acc[mt][nt], ah[mt], &bl[nt*2]);
                    mma16816(acc[mt][nt], al[mt], &bh[nt*2]);
                }
        }
    }

    // store x3 (+b3) as fp16 in layout [n][co/8][tv][co%8]
    #pragma unroll
    for (int mt = 0; mt < 2; mt++) {
        int r0 = m0 + mt*16 + (lane >> 2);
        #pragma unroll
        for (int nt = 0; nt < 8; nt++) {
            int c = n0 + nt*8 + (lane & 3)*2;
            float2 bb = *(const float2*)(b3 + c);
            __half2 h0 = __floats2half2_rn(acc[mt][nt][0] + bb.x, acc[mt][nt][1] + bb.y);
            __half2 h1 = __floats2half2_rn(acc[mt][nt][2] + bb.x, acc[mt][nt][3] + bb.y);
            size_t base = (((size_t)n*32 + (c >> 3))*TV + tv0) * 8 + (c & 7);
            if (r0 < rows)     *(__half2*)(g_x3h + base + (size_t)(r0    )*8) = h0;
            if (r0 + 8 < rows) *(__half2*)(g_x3h + base + (size_t)(r0 + 8)*8) = h1;
        }
    }
}

// ---------------- K: out — CTA (n, 8co); warp = (co-pair, 16t); LDS.64 feeds 2 FMA ----------------
__global__ __launch_bounds__(512) void k_out(float* __restrict__ out) {
    __shared__ __align__(16) float attn_s[8*700];
    __shared__ __align__(16) float x3_s[TT*VV*8];
    int n = blockIdx.y, cb = blockIdx.x;
    int co0 = cb*8;
    int tid = threadIdx.x;

    const float* ab = g_attn + ((size_t)n*CO + co0)*UV;
    for (int i = tid; i < 8*700; i += 512) {
        int co = i / 700, rem = i - co*700;
        int u = rem / 28, v = rem - u*28;
        attn_s[i] = (v < VV) ? ab[co*UV + u*VV + v] : 0.f;
    }
    // contiguous 25.6KB fp16 stream -> convert in regs -> float x3_s
    {
        const uint4* xb4 = (const uint4*)(g_x3h + ((size_t)n*32 + cb)*TV*8);  // 1600 uint4
        float4* xs4 = (float4*)x3_s;
        #pragma unroll
        for (int it = 0; it < 4; it++) {
            int idx = tid + it*512;
            if (idx < 1600) {
                uint4 d = xb4[idx];
                const __half2* hp = (const __half2*)&d;
                float2 f0 = __half22float2(hp[0]);
                float2 f1 = __half22float2(hp[1]);
                float2 f2 = __half22float2(hp[2]);
                float2 f3 = __half22float2(hp[3]);
                xs4[idx*2]     = make_float4(f0.x, f0.y, f1.x, f1.y);
                xs4[idx*2 + 1] = make_float4(f2.x, f2.y, f3.x, f3.y);
            }
        }
    }
    __syncthreads();

    int lane = tid & 31, wid = tid >> 5;
    int cp = wid & 3, tg = wid >> 2;    // co-pair index (0..3), t-group of 16 (0..3)
    int col = cp*2;                     // local co of pair start
    // preload attn rows for both co's of the pair
    float a0[VV], a1[VV];
    const float* ar0 = attn_s + (col    )*700 + lane;
    const float* ar1 = attn_s + (col + 1)*700 + lane;
    #pragma unroll
    for (int u = 0; u < VV; u++) { a0[u] = ar0[u*28]; a1[u] = ar1[u*28]; }

    size_t ob0 = (((size_t)(n*CO + co0 + col))*TT + tg*16)*VV + lane;
    size_t ob1 = ob0 + (size_t)TT*VV;   // next co
    const float* x3b = x3_s + (tg*16*VV)*8 + col;

    for (int ti = 0; ti < 16; ti++) {
        const float* xr = x3b + ti*VV*8;
        float s0 = 0.f, s1 = 0.f;
        #pragma unroll
        for (int u = 0; u < VV; u++) {
            float2 xv = *(const float2*)(xr + u*8);   // broadcast LDS.64: x3[u][co], x3[u][co+1]
            s0 += a0[u]*xv.x;
            s1 += a1[u]*xv.y;
        }
        if (lane < VV) {
            out[ob0 + (size_t)ti*VV] = s0;
            out[ob1 + (size_t)ti*VV] = s1;
        }
    }
}

// ---------------- launch (k_attn in profiled slot 4) ----------------
extern "C" void kernel_launch(void* const* d_in, const int* in_sizes, int n_in,
                              void* d_out, int out_size) {
    const float* x  = (const float*)d_in[0];
    const float* A  = (const float*)d_in[1];
    const float* w1 = (const float*)d_in[2];
    const float* b1 = (const float*)d_in[3];
    const float* w2 = (const float*)d_in[4];
    const float* b2 = (const float*)d_in[5];
    const float* w3 = (const float*)d_in[6];
    const float* b3 = (const float*)d_in[7];
    const float* w4 = (const float*)d_in[8];
    const float* b4 = (const float*)d_in[9];
    float* out = (float*)d_out;

    cudaFuncSetAttribute(k_mma, cudaFuncAttributeMaxDynamicSharedMemorySize, MMA_SMEM);

    k_xm   <<<dim3(64, 64), 256>>>(x);            // 1
    k_x12  <<<64, 256>>>(w1, b1, w2, b2);         // 2
    k_aff  <<<64, 256>>>();                       // 3
    k_attn <<<dim3(10, 4, 64), 256>>>(w4, b4, A); // 4  <-- profiled
    k_w3cvt<<<64, 1024>>>(w3);                    // 5
    k_mma  <<<dim3(13, 64), 512, MMA_SMEM>>>(x, b3); // 6
    k_out  <<<dim3(32, 64), 512>>>(out);          // 7
}

// round 17
// speedup vs baseline: 1.2735x; 1.1855x over previous
#include <cuda_runtime.h>
#include <cuda_bf16.h>
#include <cuda_fp16.h>
#include <cstdint>

#define NN 64
#define CI 256
#define CO 256
#define CR 32
#define TT 64
#define VV 25
#define TV 1600   // T*V
#define UV 625    // V*V
#define NROWS (NN*TV)       // 102400

// ---------------- scratch ----------------
__device__ float g_xm[NN*CI*VV];
__device__ float g_x1[NN*CR*VV];
__device__ float g_x2[NN*CR*VV];
__device__ float g_aff[NN*CR*UV];
__device__ float g_attn[NN*CO*UV];     // (n, co, u*25+v)
__device__ __half g_w3h[CO*CI];        // fp16(w3) [co, c]
__device__ __half g_x3h[(size_t)NROWS*CO]; // fp16, layout: [n][co/8][tv][co%8]

// ---------------- helpers ----------------
__device__ __forceinline__ uint32_t smem_u32(const void* p) {
    uint32_t a;
    asm("{ .reg .u64 t; cvta.to.shared.u64 t, %1; cvt.u32.u64 %0, t; }" : "=r"(a) : "l"(p));
    return a;
}
#define CPA(dst, src) asm volatile("cp.async.cg.shared.global [%0], [%1], 16;" \
                                   :: "r"(dst), "l"(src) : "memory")
#define CPC() asm volatile("cp.async.commit_group;" ::: "memory")
#define CPW(n) asm volatile("cp.async.wait_group %0;" :: "n"(n) : "memory")

__device__ __forceinline__ void ldsm4(uint32_t& r0, uint32_t& r1, uint32_t& r2, uint32_t& r3,
                                      uint32_t a) {
    asm volatile("ldmatrix.sync.aligned.m8n8.x4.shared.b16 {%0,%1,%2,%3}, [%4];"
                 : "=r"(r0), "=r"(r1), "=r"(r2), "=r"(r3) : "r"(a));
}
__device__ __forceinline__ void mma16816h(float* d, const uint32_t* a, const uint32_t* b) {
    asm volatile("mma.sync.aligned.m16n8k16.row.col.f32.f16.f16.f32 "
                 "{%0,%1,%2,%3}, {%4,%5,%6,%7}, {%8,%9}, {%0,%1,%2,%3};"
                 : "+f"(d[0]), "+f"(d[1]), "+f"(d[2]), "+f"(d[3])
                 : "r"(a[0]), "r"(a[1]), "r"(a[2]), "r"(a[3]), "r"(b[0]), "r"(b[1]));
}

// ---------------- K: xm = mean_t x ----------------
__global__ void k_xm(const float* __restrict__ x) {
    __shared__ float sx[4*TV];
    int n = blockIdx.y, cc = blockIdx.x;
    const float* xb = x + ((size_t)(n*CI + cc*4))*TV;
    for (int i = threadIdx.x; i < 4*TV; i += 256) sx[i] = xb[i];
    __syncthreads();
    if (threadIdx.x < 100) {
        int c = threadIdx.x / VV, v = threadIdx.x - c*VV;
        float s = 0.f;
        #pragma unroll
        for (int t = 0; t < TT; t++) s += sx[c*TV + t*VV + v];
        g_xm[n*(CI*VV) + cc*100 + threadIdx.x] = s * (1.0f/64.0f);
    }
}

// ---------------- K: x1/x2 ----------------
__global__ void k_x12(const float* __restrict__ w1, const float* __restrict__ b1,
                      const float* __restrict__ w2, const float* __restrict__ b2) {
    __shared__ float xm_s[CI*VV];
    int n = blockIdx.x;
    for (int i = threadIdx.x; i < CI*VV; i += 256) xm_s[i] = g_xm[n*(CI*VV) + i];
    __syncthreads();
    for (int i = threadIdx.x; i < 2*CR*VV; i += 256) {
        int sel = i / (CR*VV);
        int rv  = i - sel*(CR*VV);
        int r = rv / VV, v = rv - r*VV;
        const float* w = sel ? w2 : w1;
        float s = sel ? b2[r] : b1[r];
        #pragma unroll 8
        for (int c = 0; c < CI; c++) s += w[r*CI + c] * xm_s[c*VV + v];
        (sel ? g_x2 : g_x1)[n*(CR*VV) + rv] = s;
    }
}

// ---------------- K: aff = tanh(x1[u] - x2[v]) ----------------
__global__ void k_aff() {
    __shared__ float s1[CR*VV], s2[CR*VV];
    int n = blockIdx.x;
    for (int i = threadIdx.x; i < CR*VV; i += 256) {
        s1[i] = g_x1[n*(CR*VV) + i];
        s2[i] = g_x2[n*(CR*VV) + i];
    }
    __syncthreads();
    for (int i = threadIdx.x; i < CR*UV; i += 256) {
        int r = i / UV, uv = i - r*UV;
        int u = uv / VV, v = uv - u*VV;
        g_aff[n*(CR*UV) + i] = tanhf(s1[r*VV + u] - s2[r*VV + v]);
    }
}

// ---------------- K: attn = w4@aff + b4 + A  (w4 transposed in smem) ----------------
__global__ void k_attn(const float* __restrict__ w4, const float* __restrict__ b4,
                       const float* __restrict__ A) {
    __shared__ __align__(16) float w4s[CR*66];
    __shared__ __align__(16) float affs[CR*64];
    int n = blockIdx.z, cot = blockIdx.y, uvt = blockIdx.x;
    int co0 = cot*64, uv0 = uvt*64;
    int tx = threadIdx.x & 15, ty = threadIdx.x >> 4;

    for (int i = threadIdx.x; i < 64*CR; i += 256) {
        int co = i >> 5, k = i & 31;
        w4s[k*66 + co] = w4[(co0 + co)*CR + k];
    }
    for (int i = threadIdx.x; i < CR*64; i += 256) {
        int r = i >> 6, c = i & 63;
        affs[i] = (uv0 + c < UV) ? g_aff[n*(CR*UV) + r*UV + uv0 + c] : 0.f;
    }
    __syncthreads();

    float acc[4][4] = {};
    #pragma unroll
    for (int k = 0; k < CR; k++) {
        float4 b = *(const float4*)&affs[k*64 + tx*4];
        float2 a01 = *(const float2*)&w4s[k*66 + ty*4];
        float2 a23 = *(const float2*)&w4s[k*66 + ty*4 + 2];
        float av[4] = {a01.x, a01.y, a23.x, a23.y};
        #pragma unroll
        for (int i = 0; i < 4; i++) {
            acc[i][0] += av[i]*b.x; acc[i][1] += av[i]*b.y;
            acc[i][2] += av[i]*b.z; acc[i][3] += av[i]*b.w;
        }
    }
    #pragma unroll
    for (int i = 0; i < 4; i++) {
        int co = co0 + ty*4 + i;
        float bb = b4[co];
        #pragma unroll
        for (int j = 0; j < 4; j++) {
            int uv = uv0 + tx*4 + j;
            if (uv < UV)
                g_attn[((size_t)n*CO + co)*UV + uv] = acc[i][j] + bb + A[uv];
        }
    }
}

// ---------------- K: w3 -> fp16 ----------------
__global__ void k_w3cvt(const float* __restrict__ w3) {
    int i = blockIdx.x*1024 + threadIdx.x;
    g_w3h[i] = __float2half(w3[i]);
}

// ---------------- K: fused convert + fp16 HMMA GEMM  x3 = x @ w3^T + b3 ----------------
// smem: XF fp32 [c][tv] 16K x2 | A fp16 [tv][c] 10K x2 | B fp16 [co][c] 20K x3  = 112K
#define XF_OFF 0
#define XF_SZ  16384
#define A_OFF  32768
#define A_SZ   10240
#define B_OFF  53248
#define B_SZ   20480
#define MMA_SMEM 114688

__global__ __launch_bounds__(512) void k_mma(const float* __restrict__ x,
                                             const float* __restrict__ b3) {
    extern __shared__ __align__(1024) char smem[];
    uint32_t sb = smem_u32(smem);
    int tid = threadIdx.x, lane = tid & 31, wid = tid >> 5;
    int tile = blockIdx.x, n = blockIdx.y;
    int tv0 = tile * 128;
    int rows = (TV - tv0 >= 128) ? 128 : (TV - tv0);
    const float* xb = x + ((size_t)n*CI)*TV + tv0;

    auto loadX = [&](int kb, int s) {
        uint32_t xo = sb + XF_OFF + s*XF_SZ;
        #pragma unroll
        for (int it = 0; it < 2; it++) {
            int idx = tid + it*512;
            int c = idx >> 5, q = idx & 31;
            int tq = (q*4 < rows) ? q : 0;
            CPA(xo + c*512 + q*16, xb + (size_t)(kb*32 + c)*TV + tq*4);
        }
    };
    auto loadB = [&](int kb, int bs) {
        uint32_t bo = sb + B_OFF + bs*B_SZ;
        #pragma unroll
        for (int it = 0; it < 2; it++) {
            int idx = tid + it*512;              // 1024 = 256 co x 4 q
            int co = idx >> 2, q = idx & 3;
            CPA(bo + co*80 + q*16, g_w3h + co*256 + kb*32 + q*8);
        }
    };
    auto convert = [&](int s) {
        const char* xf = smem + XF_OFF + s*XF_SZ;
        char* ad = smem + A_OFF + s*A_SZ;
        int tv = tid & 127, cg = tid >> 7;
        const float* col = (const float*)(xf + cg*8*512 + tv*4);
        uint32_t hv[4];
        #pragma unroll
        for (int j = 0; j < 4; j++) {
            float v0 = col[(2*j)*128];
            float v1 = col[(2*j+1)*128];
            __half2 hh = __floats2half2_rn(v0, v1);
            hv[j] = *(uint32_t*)&hh;
        }
        *(uint4*)(ad + tv*80 + cg*16) = make_uint4(hv[0], hv[1], hv[2], hv[3]);
    };

    loadX(0, 0); loadB(0, 0); CPC();
    loadX(1, 1); loadB(1, 1); CPC();

    int m0 = (wid & 3)*32, n0 = (wid >> 2)*64;
    float acc[2][8][4];
    #pragma unroll
    for (int mt = 0; mt < 2; mt++)
        #pragma unroll
        for (int nt = 0; nt < 8; nt++)
            #pragma unroll
            for (int k = 0; k < 4; k++) acc[mt][nt][k] = 0.f;

    int a_row = lane & 15, a_seg = lane >> 4;
    int b_row = ((lane >> 4) & 1)*8 + (lane & 7), b_seg = (lane >> 3) & 1;

    #pragma unroll
    for (int kb = 0; kb < 8; kb++) {
        if (kb < 7) { CPW(1); } else { CPW(0); }
        __syncthreads();
        convert(kb & 1);
        __syncthreads();
        if (kb < 6) { loadX(kb + 2, kb & 1); loadB(kb + 2, (kb + 2) % 3); CPC(); }
        uint32_t ao = sb + A_OFF + (kb & 1)*A_SZ;
        uint32_t bo = sb + B_OFF + (kb % 3)*B_SZ;
        #pragma unroll
        for (int ks = 0; ks < 2; ks++) {
            uint32_t ah[2][4], bh[16];
            #pragma unroll
            for (int mt = 0; mt < 2; mt++) {
                uint32_t off = (uint32_t)((m0 + mt*16 + a_row)*80 + ks*32 + a_seg*16);
                ldsm4(ah[mt][0], ah[mt][1], ah[mt][2], ah[mt][3], ao + off);
            }
            #pragma unroll
            for (int np = 0; np < 4; np++) {
                uint32_t off = (uint32_t)((n0 + np*16 + b_row)*80 + ks*32 + b_seg*16);
                ldsm4(bh[np*4+0], bh[np*4+1], bh[np*4+2], bh[np*4+3], bo + off);
            }
            #pragma unroll
            for (int mt = 0; mt < 2; mt++)
                #pragma unroll
                for (int nt = 0; nt < 8; nt++)
                    mma16816h(acc[mt][nt], ah[mt], &bh[nt*2]);
        }
    }

    // store x3 (+b3) as fp16 in layout [n][co/8][tv][co%8]
    #pragma unroll
    for (int mt = 0; mt < 2; mt++) {
        int r0 = m0 + mt*16 + (lane >> 2);
        #pragma unroll
        for (int nt = 0; nt < 8; nt++) {
            int c = n0 + nt*8 + (lane & 3)*2;
            float2 bb = *(const float2*)(b3 + c);
            __half2 h0 = __floats2half2_rn(acc[mt][nt][0] + bb.x, acc[mt][nt][1] + bb.y);
            __half2 h1 = __floats2half2_rn(acc[mt][nt][2] + bb.x, acc[mt][nt][3] + bb.y);
            size_t base = (((size_t)n*32 + (c >> 3))*TV + tv0) * 8 + (c & 7);
            if (r0 < rows)     *(__half2*)(g_x3h + base + (size_t)(r0    )*8) = h0;
            if (r0 + 8 < rows) *(__half2*)(g_x3h + base + (size_t)(r0 + 8)*8) = h1;
        }
    }
}

// ---------------- K: out — CTA (n, 8co); warp = (co-pair, 16t); LDS.64 feeds 2 FMA ----------------
__global__ __launch_bounds__(512) void k_out(float* __restrict__ out) {
    __shared__ __align__(16) float attn_s[8*700];
    __shared__ __align__(16) float x3_s[TT*VV*8];
    int n = blockIdx.y, cb = blockIdx.x;
    int co0 = cb*8;
    int tid = threadIdx.x;

    const float* ab = g_attn + ((size_t)n*CO + co0)*UV;
    for (int i = tid; i < 8*700; i += 512) {
        int co = i / 700, rem = i - co*700;
        int u = rem / 28, v = rem - u*28;
        attn_s[i] = (v < VV) ? ab[co*UV + u*VV + v] : 0.f;
    }
    {
        const uint4* xb4 = (const uint4*)(g_x3h + ((size_t)n*32 + cb)*TV*8);
        float4* xs4 = (float4*)x3_s;
        #pragma unroll
        for (int it = 0; it < 4; it++) {
            int idx = tid + it*512;
            if (idx < 1600) {
                uint4 d = xb4[idx];
                const __half2* hp = (const __half2*)&d;
                float2 f0 = __half22float2(hp[0]);
                float2 f1 = __half22float2(hp[1]);
                float2 f2 = __half22float2(hp[2]);
                float2 f3 = __half22float2(hp[3]);
                xs4[idx*2]     = make_float4(f0.x, f0.y, f1.x, f1.y);
                xs4[idx*2 + 1] = make_float4(f2.x, f2.y, f3.x, f3.y);
            }
        }
    }
    __syncthreads();

    int lane = tid & 31, wid = tid >> 5;
    int cp = wid & 3, tg = wid >> 2;
    int col = cp*2;
    float a0[VV], a1[VV];
    const float* ar0 = attn_s + (col    )*700 + lane;
    const float* ar1 = attn_s + (col + 1)*700 + lane;
    #pragma unroll
    for (int u = 0; u < VV; u++) { a0[u] = ar0[u*28]; a1[u] = ar1[u*28]; }

    size_t ob0 = (((size_t)(n*CO + co0 + col))*TT + tg*16)*VV + lane;
    size_t ob1 = ob0 + (size_t)TT*VV;
    const float* x3b = x3_s + (tg*16*VV)*8 + col;

    for (int ti = 0; ti < 16; ti++) {
        const float* xr = x3b + ti*VV*8;
        float s0 = 0.f, s1 = 0.f;
        #pragma unroll
        for (int u = 0; u < VV; u++) {
            float2 xv = *(const float2*)(xr + u*8);
            s0 += a0[u]*xv.x;
            s1 += a1[u]*xv.y;
        }
        if (lane < VV) {
            out[ob0 + (size_t)ti*VV] = s0;
            out[ob1 + (size_t)ti*VV] = s1;
        }
    }
}

// ---------------- launch (k_attn in profiled slot 4) ----------------
extern "C" void kernel_launch(void* const* d_in, const int* in_sizes, int n_in,
                              void* d_out, int out_size) {
    const float* x  = (const float*)d_in[0];
    const float* A  = (const float*)d_in[1];
    const float* w1 = (const float*)d_in[2];
    const float* b1 = (const float*)d_in[3];
    const float* w2 = (const float*)d_in[4];
    const float* b2 = (const float*)d_in[5];
    const float* w3 = (const float*)d_in[6];
    const float* b3 = (const float*)d_in[7];
    const float* w4 = (const float*)d_in[8];
    const float* b4 = (const float*)d_in[9];
    float* out = (float*)d_out;

    cudaFuncSetAttribute(k_mma, cudaFuncAttributeMaxDynamicSharedMemorySize, MMA_SMEM);

    k_xm   <<<dim3(64, 64), 256>>>(x);            // 1
    k_x12  <<<64, 256>>>(w1, b1, w2, b2);         // 2
    k_aff  <<<64, 256>>>();                       // 3
    k_attn <<<dim3(10, 4, 64), 256>>>(w4, b4, A); // 4  <-- profiled
    k_w3cvt<<<64, 1024>>>(w3);                    // 5
    k_mma  <<<dim3(13, 64), 512, MMA_SMEM>>>(x, b3); // 6
    k_out  <<<dim3(32, 64), 512>>>(out);          // 7
}